// round 10
// baseline (speedup 1.0000x reference)
#include <cuda_runtime.h>
#include <cuda_bf16.h>
#include <cuda_fp16.h>
#include <cstdint>
#include <cstddef>

#define DI 4096
#define DO 4096
#define MT 8192
#define RANK 8
#define LORA_SCALE 2.0f

// ---------------- scratch (device globals; no allocation allowed) ----------------
__device__ float g_A_eff[RANK * DI];            // fwht-folded A  (8 x 4096)
__device__ float g_B_eff[DO * RANK];            // fwht-folded B  (4096 x 8), row-major [o][r]
__device__ __half g_W_h[(size_t)DO * DI];
__device__ __half g_x_h[(size_t)MT * DI];

__device__ __forceinline__ uint32_t smem_u32(const void* p) {
    uint32_t a;
    asm("{ .reg .u64 t; cvta.to.shared.u64 t, %1; cvt.u32.u64 %0, t; }" : "=r"(a) : "l"(p));
    return a;
}

// ---------------- prep kernel 1 (fused): FWHT fold (blocks 0..15) + x -> fp16 (4 float4/thread) ----------------
#define W4 ((DO * DI) / 4)              // float4 groups in W
#define X4 ((MT * DI) / 4)              // float4 groups in x
#define XBLOCKS (X4 / (512 * 4))        // 4096 blocks, 4 float4 per thread

__global__ void prep1_kernel(const float* __restrict__ Amat, const float* __restrict__ Bmat,
                             const float* __restrict__ in_signs, const float* __restrict__ out_signs,
                             const int* __restrict__ in_perm, const int* __restrict__ out_perm,
                             const float* __restrict__ x) {
    int bx = blockIdx.x;
    int tid = threadIdx.x;        // 512 threads
    if (bx >= 16) {
        // ---- x -> fp16, 4 independent float4s per thread (MLP=4) ----
        size_t base = ((size_t)(bx - 16) * 2048 + tid * 4) * 4;   // in floats
        float4 w0 = *reinterpret_cast<const float4*>(x + base);
        float4 w1 = *reinterpret_cast<const float4*>(x + base + 4);
        float4 w2 = *reinterpret_cast<const float4*>(x + base + 8);
        float4 w3 = *reinterpret_cast<const float4*>(x + base + 12);
        __half2* H = reinterpret_cast<__half2*>(g_x_h + base);
        H[0] = __halves2half2(__float2half_rn(w0.x), __float2half_rn(w0.y));
        H[1] = __halves2half2(__float2half_rn(w0.z), __float2half_rn(w0.w));
        H[2] = __halves2half2(__float2half_rn(w1.x), __float2half_rn(w1.y));
        H[3] = __halves2half2(__float2half_rn(w1.z), __float2half_rn(w1.w));
        H[4] = __halves2half2(__float2half_rn(w2.x), __float2half_rn(w2.y));
        H[5] = __halves2half2(__float2half_rn(w2.z), __float2half_rn(w2.w));
        H[6] = __halves2half2(__float2half_rn(w3.x), __float2half_rn(w3.y));
        H[7] = __halves2half2(__float2half_rn(w3.z), __float2half_rn(w3.w));
        return;
    }
    // ---- FWHT fold (blocks 0..7 -> A_eff rows, 8..15 -> B_eff cols) ----
    __shared__ float buf[DI];
    if (bx < RANK) {
        int r = bx;
        for (int j = tid; j < DI; j += 512) {
            int p = in_perm[j];
            buf[j] = in_signs[p] * Amat[r * DI + p];
        }
    } else {
        int r = bx - RANK;
        for (int j = tid; j < DO; j += 512) {
            int p = out_perm[j];
            buf[j] = out_signs[p] * Bmat[p * RANK + r];
        }
    }
    for (int h = 1; h < DI; h <<= 1) {
        __syncthreads();
        for (int t = tid; t < DI / 2; t += 512) {
            int i = ((t & ~(h - 1)) << 1) | (t & (h - 1));
            float u = buf[i], v = buf[i + h];
            buf[i] = u + v;
            buf[i + h] = u - v;
        }
    }
    __syncthreads();
    const float s = 1.0f / 64.0f;   // 1/sqrt(4096)
    if (bx < RANK) {
        int r = bx;
        for (int j = tid; j < DI; j += 512) g_A_eff[r * DI + j] = buf[j] * s;
    } else {
        int r = bx - RANK;
        for (int j = tid; j < DO; j += 512) g_B_eff[j * RANK + r] = buf[j] * s;
    }
}

// ---------------- prep kernel 2: W_eff = W + SCALE * B_eff @ A_eff -> fp16 (2 float4/thread) ----------------
__global__ void prep2_kernel(const float* __restrict__ W) {
    int gid = blockIdx.x * blockDim.x + threadIdx.x;
    size_t base = (size_t)gid * 8;            // 8 floats, same output row (4096 % 8 == 0)
    int o = (int)(base >> 12);
    int i = (int)(base & 4095);
    float4 w0 = *reinterpret_cast<const float4*>(W + base);
    float4 w1 = *reinterpret_cast<const float4*>(W + base + 4);
#pragma unroll
    for (int r = 0; r < RANK; r++) {
        float bv = LORA_SCALE * g_B_eff[o * RANK + r];
        float4 a0 = *reinterpret_cast<const float4*>(g_A_eff + r * DI + i);
        float4 a1 = *reinterpret_cast<const float4*>(g_A_eff + r * DI + i + 4);
        w0.x += bv * a0.x; w0.y += bv * a0.y; w0.z += bv * a0.z; w0.w += bv * a0.w;
        w1.x += bv * a1.x; w1.y += bv * a1.y; w1.z += bv * a1.z; w1.w += bv * a1.w;
    }
    __half2* H = reinterpret_cast<__half2*>(g_W_h + base);
    H[0] = __halves2half2(__float2half_rn(w0.x), __float2half_rn(w0.y));
    H[1] = __halves2half2(__float2half_rn(w0.z), __float2half_rn(w0.w));
    H[2] = __halves2half2(__float2half_rn(w1.x), __float2half_rn(w1.y));
    H[3] = __halves2half2(__float2half_rn(w1.z), __float2half_rn(w1.w));
}

// ---------------- main GEMM: out[8192,4096] = x @ W_eff^T + b (single fp16 product) ----------------
// Persistent CTAs: CTA 128x128, 4 warps (64x64 each), 3-stage ring running
// continuously across tiles (flat virtual-chunk pipeline), 2 CTAs/SM.
#define CTA_M 128
#define CTA_N 128
#define KC 64                   // fp16 elems per K chunk = 128B per row
#define NCHUNK (DI / KC)        // 64
#define NTILE_N (DO / CTA_N)    // 32
#define NTILES ((MT / CTA_M) * NTILE_N)  // 2048
#define STAGES 3
#define SA 0
#define SB 16384
#define STAGE_BYTES 32768
#define SMEM_TOTAL (STAGES * STAGE_BYTES)   // 96 KB -> 2 CTAs/SM

// swizzled smem offset for row r (128B rows), 16B-chunk c (0..7)
__device__ __forceinline__ uint32_t swz(int r, int c) {
    return (uint32_t)(r * 128 + ((c ^ (r & 7)) << 4));
}

__device__ __forceinline__ void cp16(uint32_t dst, const void* src) {
    asm volatile("cp.async.cg.shared.global [%0], [%1], 16;" :: "r"(dst), "l"(src));
}

__device__ __forceinline__ void ldsm4(uint32_t addr, uint32_t* r) {
    asm volatile("ldmatrix.sync.aligned.m8n8.x4.shared.b16 {%0,%1,%2,%3}, [%4];"
                 : "=r"(r[0]), "=r"(r[1]), "=r"(r[2]), "=r"(r[3]) : "r"(addr));
}

__device__ __forceinline__ void mma16816(float* c, const uint32_t* a, uint32_t b0, uint32_t b1) {
    asm volatile(
        "mma.sync.aligned.m16n8k16.row.col.f32.f16.f16.f32 "
        "{%0,%1,%2,%3}, {%4,%5,%6,%7}, {%8,%9}, {%0,%1,%2,%3};"
        : "+f"(c[0]), "+f"(c[1]), "+f"(c[2]), "+f"(c[3])
        : "r"(a[0]), "r"(a[1]), "r"(a[2]), "r"(a[3]), "r"(b0), "r"(b1));
}

__device__ __forceinline__ void load_stage(uint32_t stage, int chunk, int m0, int n0, int tid) {
    int k0 = chunk * KC;
    const char* xh = (const char*)(g_x_h + (size_t)m0 * DI + k0);
    const char* wh = (const char*)(g_W_h + (size_t)n0 * DI + k0);
#pragma unroll
    for (int i = 0; i < 8; i++) {           // A: 128 rows x 8 chunks of 16B
        int idx = tid + i * 128;
        int r = idx >> 3, c = idx & 7;
        cp16(stage + SA + swz(r, c), xh + (size_t)r * (DI * 2) + c * 16);
    }
#pragma unroll
    for (int i = 0; i < 8; i++) {           // B: 128 rows x 8 chunks
        int idx = tid + i * 128;
        int r = idx >> 3, c = idx & 7;
        cp16(stage + SB + swz(r, c), wh + (size_t)r * (DI * 2) + c * 16);
    }
    asm volatile("cp.async.commit_group;" ::: "memory");
}

struct Frags {
    uint32_t a[4][4];
    uint32_t b[4][4];
};

__device__ __forceinline__ void load_frags(uint32_t stage, int kk, Frags& f,
                                           int lane, int warp_m, int warp_n) {
    int lane15 = lane & 15;
    int lanehi = lane >> 4;
    int ca = kk * 2 + lanehi;
#pragma unroll
    for (int mt = 0; mt < 4; mt++) {
        int r = warp_m * 64 + mt * 16 + lane15;
        ldsm4(stage + SA + swz(r, ca), f.a[mt]);
    }
    int nb = warp_n * 64 + (lane & 7) + ((lane >> 4) << 3);
    int cb = kk * 2 + ((lane >> 3) & 1);
#pragma unroll
    for (int np = 0; np < 4; np++)
        ldsm4(stage + SB + swz(nb + np * 16, cb), f.b[np]);
}

__device__ __forceinline__ void mma_frags(const Frags& f, float (*acc)[8][4]) {
#pragma unroll
    for (int mt = 0; mt < 4; mt++)
#pragma unroll
        for (int nt = 0; nt < 8; nt++)
            mma16816(acc[mt][nt], f.a[mt],
                     f.b[nt >> 1][(nt & 1) * 2], f.b[nt >> 1][(nt & 1) * 2 + 1]);
}

__global__ void __launch_bounds__(128, 2)
gemm_kernel(const float* __restrict__ bias, float* __restrict__ out) {
    extern __shared__ char smem[];
    uint32_t sb = smem_u32(smem);
    int tid = threadIdx.x;
    int lane = tid & 31;
    int wid = tid >> 5;              // 4 warps: warp_m = wid>>1, warp_n = wid&1
    int warp_m = wid >> 1;
    int warp_n = wid & 1;
    int bid = blockIdx.x;
    int G = gridDim.x;

    int ntile = (NTILES - 1 - bid) / G + 1;    // tiles for this CTA: bid, bid+G, ...
    int total = ntile * NCHUNK;                 // virtual chunks

    float acc[4][8][4];
#pragma unroll
    for (int a = 0; a < 4; a++)
#pragma unroll
        for (int b = 0; b < 8; b++)
#pragma unroll
            for (int c = 0; c < 4; c++) acc[a][b][c] = 0.0f;

    // tile coords of virtual chunk v: t = bid + (v>>6)*G; n0=(t&31)*128, m0=(t>>5)*128
    int t0 = bid;
    int m0 = (t0 >> 5) * CTA_M;
    int n0 = (t0 & 31) * CTA_N;

    // prologue: virtual chunks 0 and 1 (same tile since NCHUNK=64>1)
    load_stage(sb + 0 * STAGE_BYTES, 0, m0, n0, tid);
    load_stage(sb + 1 * STAGE_BYTES, 1, m0, n0, tid);

    Frags fr[2];
    asm volatile("cp.async.wait_group %0;" :: "n"(1) : "memory");
    __syncthreads();
    load_frags(sb + 0 * STAGE_BYTES, 0, fr[0], lane, warp_m, warp_n);

    int sc = 0;                        // stage of current virtual chunk
    int sr = 2;                        // stage of virtual chunk v+2
#pragma unroll 1
    for (int v = 0; v < total; v++) {
        int ci = v & (NCHUNK - 1);
        uint32_t stage = sb + sc * STAGE_BYTES;
        // refill: virtual chunk v+2 (possibly next tile)
        if (v + 2 < total) {
            int v2 = v + 2;
            int t2 = bid + (v2 >> 6) * G;
            load_stage(sb + sr * STAGE_BYTES, v2 & (NCHUNK - 1),
                       (t2 >> 5) * CTA_M, (t2 & 31) * CTA_N, tid);
        } else {
            asm volatile("cp.async.commit_group;" ::: "memory");
        }
        load_frags(stage, 1, fr[1], lane, warp_m, warp_n);
        mma_frags(fr[0], acc);
        load_frags(stage, 2, fr[0], lane, warp_m, warp_n);
        mma_frags(fr[1], acc);
        load_frags(stage, 3, fr[1], lane, warp_m, warp_n);
        __syncthreads();               // release stage sc for refill at iter v+1
        mma_frags(fr[0], acc);
        if (v + 1 < total) {
            asm volatile("cp.async.wait_group %0;" :: "n"(1) : "memory");  // v+1 resident
            int sn = (sc == 2) ? 0 : sc + 1;
            load_frags(sb + sn * STAGE_BYTES, 0, fr[0], lane, warp_m, warp_n);
        }
        mma_frags(fr[1], acc);

        if (ci == NCHUNK - 1) {
            // ---- epilogue for tile (overlaps next tile's first-chunk compute) ----
            int t = bid + (v >> 6) * G;
            int em0 = (t >> 5) * CTA_M;
            int en0 = (t & 31) * CTA_N;
            int g = lane >> 2, tt = lane & 3;
            int col0 = en0 + warp_n * 64;
#pragma unroll
            for (int mt = 0; mt < 4; mt++) {
                int r0 = em0 + warp_m * 64 + mt * 16 + g;
                float* p0 = out + (size_t)r0 * DO;
                float* p1 = out + (size_t)(r0 + 8) * DO;
#pragma unroll
                for (int nt = 0; nt < 8; nt++) {
                    int c = col0 + nt * 8 + tt * 2;
                    float2 bv = *reinterpret_cast<const float2*>(bias + c);
                    float2 v0, v1;
                    v0.x = acc[mt][nt][0] + bv.x;
                    v0.y = acc[mt][nt][1] + bv.y;
                    v1.x = acc[mt][nt][2] + bv.x;
                    v1.y = acc[mt][nt][3] + bv.y;
                    *reinterpret_cast<float2*>(p0 + c) = v0;
                    *reinterpret_cast<float2*>(p1 + c) = v1;
                    acc[mt][nt][0] = 0.0f; acc[mt][nt][1] = 0.0f;
                    acc[mt][nt][2] = 0.0f; acc[mt][nt][3] = 0.0f;
                }
            }
        }
        sc = (sc == 2) ? 0 : sc + 1;
        sr = (sr == 2) ? 0 : sr + 1;
    }
}

// ---------------- launch ----------------
extern "C" void kernel_launch(void* const* d_in, const int* in_sizes, int n_in,
                              void* d_out, int out_size) {
    const float* x         = (const float*)d_in[0];
    const float* W         = (const float*)d_in[1];
    const float* b         = (const float*)d_in[2];
    const float* A         = (const float*)d_in[3];
    const float* Bm        = (const float*)d_in[4];
    const float* in_signs  = (const float*)d_in[5];
    const float* out_signs = (const float*)d_in[6];
    const int*   in_perm   = (const int*)d_in[7];
    const int*   out_perm  = (const int*)d_in[9];
    float* out = (float*)d_out;

    prep1_kernel<<<16 + XBLOCKS, 512>>>(A, Bm, in_signs, out_signs, in_perm, out_perm, x);
    prep2_kernel<<<W4 / (2 * 512), 512>>>(W);

    static int grid = 0;
    if (!grid) {
        int sm = 0;
        cudaDeviceGetAttribute(&sm, cudaDevAttrMultiProcessorCount, 0);
        grid = sm * 2;
        if (grid <= 0 || grid > NTILES) grid = 296;
        cudaFuncSetAttribute(gemm_kernel, cudaFuncAttributeMaxDynamicSharedMemorySize, SMEM_TOTAL);
    }
    gemm_kernel<<<grid, 128, SMEM_TOTAL>>>(b, out);
}

// round 12
// speedup vs baseline: 1.3049x; 1.3049x over previous
#include <cuda_runtime.h>
#include <cuda_bf16.h>
#include <cuda_fp16.h>
#include <cstdint>
#include <cstddef>

#define DI 4096
#define DO 4096
#define MT 8192
#define RANK 8
#define LORA_SCALE 2.0f

// ---------------- scratch (device globals; no allocation allowed) ----------------
__device__ float g_A_eff[RANK * DI];            // fwht-folded A  (8 x 4096)
__device__ float g_B_eff[DO * RANK];            // fwht-folded B  (4096 x 8), row-major [o][r]
__device__ __half g_W_h[(size_t)DO * DI];
__device__ __half g_x_h[(size_t)MT * DI];

__device__ __forceinline__ uint32_t smem_u32(const void* p) {
    uint32_t a;
    asm("{ .reg .u64 t; cvta.to.shared.u64 t, %1; cvt.u32.u64 %0, t; }" : "=r"(a) : "l"(p));
    return a;
}

// ---------------- prep kernel 1 (fused): FWHT fold (blocks 0..15) + x -> fp16 ----------------
// x-convert: 4 float4s per thread at WARP-STRIDE spacing -> coalesced per instruction, MLP=4.
#define W4 ((DO * DI) / 4)              // float4 groups in W
#define X4 ((MT * DI) / 4)              // float4 groups in x
#define XBLOCKS (X4 / (512 * 4))        // 4096 blocks, 4 coalesced float4 per thread

__global__ void prep1_kernel(const float* __restrict__ Amat, const float* __restrict__ Bmat,
                             const float* __restrict__ in_signs, const float* __restrict__ out_signs,
                             const int* __restrict__ in_perm, const int* __restrict__ out_perm,
                             const float* __restrict__ x) {
    int bx = blockIdx.x;
    int tid = threadIdx.x;        // 512 threads
    if (bx >= 16) {
        // ---- x -> fp16: f4 indices base + tid + i*512 (coalesced, 4 in flight) ----
        size_t f4base = (size_t)(bx - 16) * 2048 + tid;
        float4 w0 = *reinterpret_cast<const float4*>(x + (f4base          ) * 4);
        float4 w1 = *reinterpret_cast<const float4*>(x + (f4base + 512    ) * 4);
        float4 w2 = *reinterpret_cast<const float4*>(x + (f4base + 1024   ) * 4);
        float4 w3 = *reinterpret_cast<const float4*>(x + (f4base + 1536   ) * 4);
        __half2* H0 = reinterpret_cast<__half2*>(g_x_h + (f4base          ) * 4);
        __half2* H1 = reinterpret_cast<__half2*>(g_x_h + (f4base + 512    ) * 4);
        __half2* H2 = reinterpret_cast<__half2*>(g_x_h + (f4base + 1024   ) * 4);
        __half2* H3 = reinterpret_cast<__half2*>(g_x_h + (f4base + 1536   ) * 4);
        H0[0] = __halves2half2(__float2half_rn(w0.x), __float2half_rn(w0.y));
        H0[1] = __halves2half2(__float2half_rn(w0.z), __float2half_rn(w0.w));
        H1[0] = __halves2half2(__float2half_rn(w1.x), __float2half_rn(w1.y));
        H1[1] = __halves2half2(__float2half_rn(w1.z), __float2half_rn(w1.w));
        H2[0] = __halves2half2(__float2half_rn(w2.x), __float2half_rn(w2.y));
        H2[1] = __halves2half2(__float2half_rn(w2.z), __float2half_rn(w2.w));
        H3[0] = __halves2half2(__float2half_rn(w3.x), __float2half_rn(w3.y));
        H3[1] = __halves2half2(__float2half_rn(w3.z), __float2half_rn(w3.w));
        return;
    }
    // ---- FWHT fold (blocks 0..7 -> A_eff rows, 8..15 -> B_eff cols) ----
    __shared__ float buf[DI];
    if (bx < RANK) {
        int r = bx;
        for (int j = tid; j < DI; j += 512) {
            int p = in_perm[j];
            buf[j] = in_signs[p] * Amat[r * DI + p];
        }
    } else {
        int r = bx - RANK;
        for (int j = tid; j < DO; j += 512) {
            int p = out_perm[j];
            buf[j] = out_signs[p] * Bmat[p * RANK + r];
        }
    }
    for (int h = 1; h < DI; h <<= 1) {
        __syncthreads();
        for (int t = tid; t < DI / 2; t += 512) {
            int i = ((t & ~(h - 1)) << 1) | (t & (h - 1));
            float u = buf[i], v = buf[i + h];
            buf[i] = u + v;
            buf[i + h] = u - v;
        }
    }
    __syncthreads();
    const float s = 1.0f / 64.0f;   // 1/sqrt(4096)
    if (bx < RANK) {
        int r = bx;
        for (int j = tid; j < DI; j += 512) g_A_eff[r * DI + j] = buf[j] * s;
    } else {
        int r = bx - RANK;
        for (int j = tid; j < DO; j += 512) g_B_eff[j * RANK + r] = buf[j] * s;
    }
}

// ---------------- prep kernel 2: W_eff = W + SCALE * B_eff @ A_eff -> fp16 ----------------
// One W row (4096 floats = 1024 float4) per block; 512 threads x 2 coalesced float4s.
__global__ void prep2_kernel(const float* __restrict__ W) {
    int o = blockIdx.x;                 // output row
    int tid = threadIdx.x;              // 512
    float bv[RANK];
#pragma unroll
    for (int r = 0; r < RANK; r++) bv[r] = LORA_SCALE * g_B_eff[o * RANK + r];

    size_t rowbase = (size_t)o * DI;
#pragma unroll
    for (int half = 0; half < 2; half++) {
        int i = (tid + half * 512) * 4;              // column within row
        float4 w = *reinterpret_cast<const float4*>(W + rowbase + i);
#pragma unroll
        for (int r = 0; r < RANK; r++) {
            float4 a = *reinterpret_cast<const float4*>(g_A_eff + r * DI + i);
            w.x += bv[r] * a.x; w.y += bv[r] * a.y; w.z += bv[r] * a.z; w.w += bv[r] * a.w;
        }
        __half2* H = reinterpret_cast<__half2*>(g_W_h + rowbase + i);
        H[0] = __halves2half2(__float2half_rn(w.x), __float2half_rn(w.y));
        H[1] = __halves2half2(__float2half_rn(w.z), __float2half_rn(w.w));
    }
}

// ---------------- main GEMM: out[8192,4096] = x @ W_eff^T + b (single fp16 product) ----------------
// CTA 128x128, 4 warps (64x64 each), 3-stage pipeline, 2 CTAs/SM co-resident.  (R9 config)
#define CTA_M 128
#define CTA_N 128
#define KC 64                   // fp16 elems per K chunk = 128B per row
#define NCHUNK (DI / KC)        // 64
#define STAGES 3
#define SA 0
#define SB 16384
#define STAGE_BYTES 32768
#define SMEM_TOTAL (STAGES * STAGE_BYTES)   // 96 KB -> 2 CTAs/SM

// swizzled smem offset for row r (128B rows), 16B-chunk c (0..7)
__device__ __forceinline__ uint32_t swz(int r, int c) {
    return (uint32_t)(r * 128 + ((c ^ (r & 7)) << 4));
}

__device__ __forceinline__ void cp16(uint32_t dst, const void* src) {
    asm volatile("cp.async.cg.shared.global [%0], [%1], 16;" :: "r"(dst), "l"(src));
}

__device__ __forceinline__ void ldsm4(uint32_t addr, uint32_t* r) {
    asm volatile("ldmatrix.sync.aligned.m8n8.x4.shared.b16 {%0,%1,%2,%3}, [%4];"
                 : "=r"(r[0]), "=r"(r[1]), "=r"(r[2]), "=r"(r[3]) : "r"(addr));
}

__device__ __forceinline__ void mma16816(float* c, const uint32_t* a, uint32_t b0, uint32_t b1) {
    asm volatile(
        "mma.sync.aligned.m16n8k16.row.col.f32.f16.f16.f32 "
        "{%0,%1,%2,%3}, {%4,%5,%6,%7}, {%8,%9}, {%0,%1,%2,%3};"
        : "+f"(c[0]), "+f"(c[1]), "+f"(c[2]), "+f"(c[3])
        : "r"(a[0]), "r"(a[1]), "r"(a[2]), "r"(a[3]), "r"(b0), "r"(b1));
}

__device__ __forceinline__ void load_stage(uint32_t stage, int chunk, int m0, int n0, int tid) {
    int k0 = chunk * KC;
    const char* xh = (const char*)(g_x_h + (size_t)m0 * DI + k0);
    const char* wh = (const char*)(g_W_h + (size_t)n0 * DI + k0);
#pragma unroll
    for (int i = 0; i < 8; i++) {           // A: 128 rows x 8 chunks of 16B
        int idx = tid + i * 128;
        int r = idx >> 3, c = idx & 7;
        cp16(stage + SA + swz(r, c), xh + (size_t)r * (DI * 2) + c * 16);
    }
#pragma unroll
    for (int i = 0; i < 8; i++) {           // B: 128 rows x 8 chunks
        int idx = tid + i * 128;
        int r = idx >> 3, c = idx & 7;
        cp16(stage + SB + swz(r, c), wh + (size_t)r * (DI * 2) + c * 16);
    }
    asm volatile("cp.async.commit_group;" ::: "memory");
}

struct Frags {
    uint32_t a[4][4];
    uint32_t b[4][4];
};

__device__ __forceinline__ void load_frags(uint32_t stage, int kk, Frags& f,
                                           int lane, int warp_m, int warp_n) {
    int lane15 = lane & 15;
    int lanehi = lane >> 4;
    int ca = kk * 2 + lanehi;
#pragma unroll
    for (int mt = 0; mt < 4; mt++) {
        int r = warp_m * 64 + mt * 16 + lane15;
        ldsm4(stage + SA + swz(r, ca), f.a[mt]);
    }
    int nb = warp_n * 64 + (lane & 7) + ((lane >> 4) << 3);
    int cb = kk * 2 + ((lane >> 3) & 1);
#pragma unroll
    for (int np = 0; np < 4; np++)
        ldsm4(stage + SB + swz(nb + np * 16, cb), f.b[np]);
}

__device__ __forceinline__ void mma_frags(const Frags& f, float (*acc)[8][4]) {
#pragma unroll
    for (int mt = 0; mt < 4; mt++)
#pragma unroll
        for (int nt = 0; nt < 8; nt++)
            mma16816(acc[mt][nt], f.a[mt],
                     f.b[nt >> 1][(nt & 1) * 2], f.b[nt >> 1][(nt & 1) * 2 + 1]);
}

__global__ void __launch_bounds__(128, 2)
gemm_kernel(const float* __restrict__ bias, float* __restrict__ out) {
    extern __shared__ char smem[];
    uint32_t sb = smem_u32(smem);
    int tid = threadIdx.x;
    int lane = tid & 31;
    int wid = tid >> 5;              // 4 warps: warp_m = wid>>1 (0..1), warp_n = wid&1 (0..1)
    int warp_m = wid >> 1;
    int warp_n = wid & 1;
    int n0 = blockIdx.x * CTA_N;
    int m0 = blockIdx.y * CTA_M;

    float acc[4][8][4];
#pragma unroll
    for (int a = 0; a < 4; a++)
#pragma unroll
        for (int b = 0; b < 8; b++)
#pragma unroll
            for (int c = 0; c < 4; c++) acc[a][b][c] = 0.0f;

    // prologue: prefetch 2 chunks
    load_stage(sb + 0 * STAGE_BYTES, 0, m0, n0, tid);
    load_stage(sb + 1 * STAGE_BYTES, 1, m0, n0, tid);

    Frags fr[2];
    asm volatile("cp.async.wait_group %0;" :: "n"(1) : "memory");  // chunk 0 resident
    __syncthreads();
    load_frags(sb + 0 * STAGE_BYTES, 0, fr[0], lane, warp_m, warp_n);

    // stage of chunk c = c % 3
    int sc = 0;                        // current stage
    int sr = 2;                        // refill stage = (chunk+2) % 3
#pragma unroll 1
    for (int chunk = 0; chunk < NCHUNK; chunk++) {
        uint32_t stage = sb + sc * STAGE_BYTES;
        // refill stage (chunk+2)%3: it was released by the early barrier of iter chunk-1
        if (chunk + 2 < NCHUNK) {
            load_stage(sb + sr * STAGE_BYTES, chunk + 2, m0, n0, tid);
        } else {
            asm volatile("cp.async.commit_group;" ::: "memory");
        }
        load_frags(stage, 1, fr[1], lane, warp_m, warp_n);
        mma_frags(fr[0], acc);
        load_frags(stage, 2, fr[0], lane, warp_m, warp_n);
        mma_frags(fr[1], acc);
        load_frags(stage, 3, fr[1], lane, warp_m, warp_n);
        // last read of this stage done -> release it; barrier latency hides under queued HMMAs
        __syncthreads();
        mma_frags(fr[0], acc);
        if (chunk + 1 < NCHUNK) {
            asm volatile("cp.async.wait_group %0;" :: "n"(1) : "memory");  // chunk+1 resident
            int sn = (sc == 2) ? 0 : sc + 1;
            load_frags(sb + sn * STAGE_BYTES, 0, fr[0], lane, warp_m, warp_n);
        }
        mma_frags(fr[1], acc);
        sc = (sc == 2) ? 0 : sc + 1;
        sr = (sr == 2) ? 0 : sr + 1;
    }

    // epilogue: add bias, store fp32
    int g = lane >> 2, t = lane & 3;
    int col0 = n0 + warp_n * 64;
    float2 bv[8];
#pragma unroll
    for (int nt = 0; nt < 8; nt++)
        bv[nt] = *reinterpret_cast<const float2*>(bias + col0 + nt * 8 + t * 2);
#pragma unroll
    for (int mt = 0; mt < 4; mt++) {
        int r0 = m0 + warp_m * 64 + mt * 16 + g;
        float* p0 = out + (size_t)r0 * DO;
        float* p1 = out + (size_t)(r0 + 8) * DO;
#pragma unroll
        for (int nt = 0; nt < 8; nt++) {
            int c = col0 + nt * 8 + t * 2;
            float2 v0, v1;
            v0.x = acc[mt][nt][0] + bv[nt].x;
            v0.y = acc[mt][nt][1] + bv[nt].y;
            v1.x = acc[mt][nt][2] + bv[nt].x;
            v1.y = acc[mt][nt][3] + bv[nt].y;
            *reinterpret_cast<float2*>(p0 + c) = v0;
            *reinterpret_cast<float2*>(p1 + c) = v1;
        }
    }
}

// ---------------- launch ----------------
extern "C" void kernel_launch(void* const* d_in, const int* in_sizes, int n_in,
                              void* d_out, int out_size) {
    const float* x         = (const float*)d_in[0];
    const float* W         = (const float*)d_in[1];
    const float* b         = (const float*)d_in[2];
    const float* A         = (const float*)d_in[3];
    const float* Bm        = (const float*)d_in[4];
    const float* in_signs  = (const float*)d_in[5];
    const float* out_signs = (const float*)d_in[6];
    const int*   in_perm   = (const int*)d_in[7];
    const int*   out_perm  = (const int*)d_in[9];
    float* out = (float*)d_out;

    prep1_kernel<<<16 + XBLOCKS, 512>>>(A, Bm, in_signs, out_signs, in_perm, out_perm, x);
    prep2_kernel<<<DO, 512>>>(W);

    static int smem_set = 0;
    if (!smem_set) {
        cudaFuncSetAttribute(gemm_kernel, cudaFuncAttributeMaxDynamicSharedMemorySize, SMEM_TOTAL);
        smem_set = 1;
    }
    gemm_kernel<<<dim3(DO / CTA_N, MT / CTA_M), 128, SMEM_TOTAL>>>(b, out);
}